// round 12
// baseline (speedup 1.0000x reference)
#include <cuda_runtime.h>
#include <cuda_fp16.h>
#include <cstdint>

#define B_ 8
#define T_ 2048
#define C_ 1024
#define H_ 64
#define NW_ 192

// ---------------------------------------------------------------------------
// Global scratch
// ---------------------------------------------------------------------------
__device__ __half g_w[NW_ * C_];
__device__ __half g_q[B_ * T_ * H_];
__device__ __half g_k[B_ * T_ * H_];
__device__ __half g_v[B_ * T_ * H_];
__device__ float g_po[B_ * 40 * 128 * 64];
__device__ float g_pl[B_ * 40 * 128];
__device__ int   g_cnt[B_ * 16];   // piece-completion tickets per (b,qb)
__device__ int   g_rdy[B_];        // proj readiness per batch

// ---------------------------------------------------------------------------
// Basic helpers
// ---------------------------------------------------------------------------
__device__ __forceinline__ uint32_t smem_u32(const void* p) {
    return (uint32_t)__cvta_generic_to_shared(p);
}
__device__ __forceinline__ void ldsm_x4(uint32_t& r0, uint32_t& r1,
                                        uint32_t& r2, uint32_t& r3, uint32_t addr) {
    asm volatile("ldmatrix.sync.aligned.m8n8.x4.shared.b16 {%0,%1,%2,%3}, [%4];"
                 : "=r"(r0), "=r"(r1), "=r"(r2), "=r"(r3) : "r"(addr));
}
__device__ __forceinline__ void ldsm_x4_t(uint32_t& r0, uint32_t& r1,
                                          uint32_t& r2, uint32_t& r3, uint32_t addr) {
    asm volatile("ldmatrix.sync.aligned.m8n8.x4.trans.shared.b16 {%0,%1,%2,%3}, [%4];"
                 : "=r"(r0), "=r"(r1), "=r"(r2), "=r"(r3) : "r"(addr));
}
__device__ __forceinline__ void mma16816h(float* d,
                                          uint32_t a0, uint32_t a1, uint32_t a2, uint32_t a3,
                                          uint32_t b0, uint32_t b1) {
    asm volatile("mma.sync.aligned.m16n8k16.row.col.f32.f16.f16.f32 "
                 "{%0,%1,%2,%3}, {%4,%5,%6,%7}, {%8,%9}, {%0,%1,%2,%3};"
                 : "+f"(d[0]), "+f"(d[1]), "+f"(d[2]), "+f"(d[3])
                 : "r"(a0), "r"(a1), "r"(a2), "r"(a3), "r"(b0), "r"(b1));
}
__device__ __forceinline__ void cp16(uint32_t dst, const void* src) {
    asm volatile("cp.async.cg.shared.global [%0], [%1], 16;" :: "r"(dst), "l"(src));
}
__device__ __forceinline__ void cp_commit() { asm volatile("cp.async.commit_group;"); }
__device__ __forceinline__ void cp_wait0()  { asm volatile("cp.async.wait_group 0;"); }

// ---------------------------------------------------------------------------
// Packed f32x2 helpers
// ---------------------------------------------------------------------------
__device__ __forceinline__ uint64_t pk2(float a, float b) {
    uint64_t r; asm("mov.b64 %0, {%1, %2};" : "=l"(r) : "f"(a), "f"(b)); return r;
}
__device__ __forceinline__ void upk2(uint64_t v, float& a, float& b) {
    asm("mov.b64 {%0, %1}, %2;" : "=f"(a), "=f"(b) : "l"(v));
}
__device__ __forceinline__ uint64_t pk2u(uint32_t a, uint32_t b) {
    uint64_t r; asm("mov.b64 %0, {%1, %2};" : "=l"(r) : "r"(a), "r"(b)); return r;
}
__device__ __forceinline__ void upk2u(uint64_t v, uint32_t& a, uint32_t& b) {
    asm("mov.b64 {%0, %1}, %2;" : "=r"(a), "=r"(b) : "l"(v));
}
__device__ __forceinline__ uint64_t f2mul(uint64_t a, uint64_t b) {
    uint64_t d; asm("mul.rn.f32x2 %0, %1, %2;" : "=l"(d) : "l"(a), "l"(b)); return d;
}
__device__ __forceinline__ uint64_t f2add(uint64_t a, uint64_t b) {
    uint64_t d; asm("add.rn.f32x2 %0, %1, %2;" : "=l"(d) : "l"(a), "l"(b)); return d;
}
__device__ __forceinline__ uint64_t f2fma(uint64_t a, uint64_t b, uint64_t c) {
    uint64_t d; asm("fma.rn.f32x2 %0, %1, %2, %3;" : "=l"(d) : "l"(a), "l"(b), "l"(c)); return d;
}
#define DUP2(x) (0x100000001ULL * (uint64_t)__float_as_uint(x))

__device__ __forceinline__ uint64_t exp_pair(uint64_t S2) {
    uint64_t Y2 = f2mul(S2, DUP2(0.045084220027780105f));
    uint64_t Z2 = f2add(Y2, DUP2(12582912.0f));
    uint64_t R2 = f2add(Z2, DUP2(-12582912.0f));
    uint64_t F2 = f2fma(R2, DUP2(-1.0f), Y2);
    uint64_t P2 = f2fma(DUP2(1.3333558e-3f), F2, DUP2(9.6181291e-3f));
    P2 = f2fma(P2, F2, DUP2(5.5504109e-2f));
    P2 = f2fma(P2, F2, DUP2(2.4022651e-1f));
    P2 = f2fma(P2, F2, DUP2(6.9314718e-1f));
    P2 = f2fma(P2, F2, DUP2(1.0f));
    uint32_t z0, z1; upk2u(Z2, z0, z1);
    uint32_t s0 = (z0 + 0xB4C0007Fu) << 23;
    uint32_t s1 = (z1 + 0xB4C0007Fu) << 23;
    return f2mul(P2, pk2u(s0, s1));
}

__device__ __forceinline__ uint32_t pkh2(float a, float b) {
    uint32_t r; asm("cvt.rn.f16x2.f32 %0, %1, %2;" : "=r"(r) : "f"(b), "f"(a)); return r;
}
__device__ __forceinline__ uint32_t pkh2p(uint64_t v2) {
    float a, b; upk2(v2, a, b);
    return pkh2(a, b);
}

// ---------------------------------------------------------------------------
// Kernel 1: weights -> fp16 (vectorized) + reset all tickets.
// ---------------------------------------------------------------------------
__global__ __launch_bounds__(256) void convert_w_kernel(const float* __restrict__ Wk,
                                                        const float* __restrict__ Wq,
                                                        const float* __restrict__ Wv) {
    if (blockIdx.x == 0) {
        if (threadIdx.x < B_ * 16) g_cnt[threadIdx.x] = 0;
        if (threadIdx.x < B_)      g_rdy[threadIdx.x] = 0;
    }
    int i4 = blockIdx.x * 256 + threadIdx.x;
    if (i4 >= NW_ * C_ / 4) return;
    int idx = i4 * 4;
    int n = idx >> 10, c = idx & 1023;
    const float* src = (n < 64) ? Wk : (n < 128) ? Wq : Wv;
    float4 v = *(const float4*)(src + (n & 63) * C_ + c);
    *(uint2*)&g_w[idx] = make_uint2(pkh2(v.x, v.y), pkh2(v.z, v.w));
}

// ---------------------------------------------------------------------------
// Fused kernel: proj (bids 0..255) | attn (256..575) | combine (576..671).
// Dependencies via global tickets; counters reset each launch by convert_w.
// ---------------------------------------------------------------------------
#define XP 24
#define PX_ST (64 * XP * 2)        // 3072
#define PW_ST (NW_ * XP * 2)       // 9216
#define AS 72
#define COMP_B (64 * AS * 2)       // 9216
#define STAGE_B (2 * COMP_B)       // 18432 (K + V)
#define FUSED_SMEM (2 * STAGE_B)   // 36864 (covers proj's 24576 too)

__device__ __forceinline__ void proj_body(const float* __restrict__ x, char* psm)
{
    __half* Xs[2] = {(__half*)psm, (__half*)(psm + PX_ST)};
    __half* Ws[2] = {(__half*)(psm + 2 * PX_ST), (__half*)(psm + 2 * PX_ST + PW_ST)};

    const int tid  = threadIdx.x;
    const int lane = tid & 31;
    const int warp = tid >> 5;
    const int m0    = blockIdx.x * 64;
    const int mrow0 = (warp >> 2) * 32;
    const int ncol0 = (warp & 3) * 48;

    const int xr = tid >> 2;
    const int xc = (tid & 3) * 4;

    float acc[2][6][4];
#pragma unroll
    for (int mt = 0; mt < 2; mt++)
#pragma unroll
        for (int nt = 0; nt < 6; nt++)
#pragma unroll
            for (int e = 0; e < 4; e++) acc[mt][nt][e] = 0.f;

    auto issue_w = [&](int kb, int s) {
#pragma unroll
        for (int rr = 0; rr < 2; rr++) {
            int c = tid + 256 * rr;
            if (c < 384) {
                int n = c >> 1, half = c & 1;
                const __half* src = g_w + (size_t)n * C_ + kb * 16 + half * 8;
                cp16(smem_u32(Ws[s] + n * XP + half * 8), src);
            }
        }
    };

    float4 nx;
    auto load_x = [&](int kb) {
        nx = *(const float4*)(x + (size_t)(m0 + xr) * C_ + kb * 16 + xc);
    };
    auto store_x = [&](int s) {
        uint32_t h01 = pkh2(nx.x, nx.y);
        uint32_t h23 = pkh2(nx.z, nx.w);
        asm volatile("st.shared.v2.b32 [%0], {%1,%2};"
                     :: "r"(smem_u32(&Xs[s][xr * XP + xc])), "r"(h01), "r"(h23));
    };

    issue_w(0, 0);
    cp_commit();
    load_x(0);
    store_x(0);
    cp_wait0();
    __syncthreads();

    for (int kb = 0; kb < 64; kb++) {
        const int s = kb & 1;
        if (kb < 63) {
            issue_w(kb + 1, s ^ 1);
            cp_commit();
            load_x(kb + 1);
        }

        const uint32_t sX = smem_u32(Xs[s]);
        const uint32_t sW = smem_u32(Ws[s]);

        uint32_t bh[6][2];
#pragma unroll
        for (int p = 0; p < 3; p++) {
            int brow = ncol0 + p * 16 + (lane & 7) + ((lane & 16) >> 1);
            int bcol = (lane & 8);
            uint32_t off = (uint32_t)(brow * XP + bcol) * 2;
            ldsm_x4(bh[2 * p][0], bh[2 * p][1], bh[2 * p + 1][0], bh[2 * p + 1][1], sW + off);
        }
#pragma unroll
        for (int mt = 0; mt < 2; mt++) {
            int arow = mrow0 + mt * 16 + (lane & 15);
            int acol = ((lane & 16) >> 1);
            uint32_t off = (uint32_t)(arow * XP + acol) * 2;
            uint32_t a[4];
            ldsm_x4(a[0], a[1], a[2], a[3], sX + off);
#pragma unroll
            for (int nt = 0; nt < 6; nt++)
                mma16816h(acc[mt][nt], a[0], a[1], a[2], a[3], bh[nt][0], bh[nt][1]);
        }
        if (kb < 63) store_x(s ^ 1);
        cp_wait0();
        __syncthreads();
    }

    const int g  = lane >> 2;
    const int c2 = (lane & 3) * 2;
#pragma unroll
    for (int mt = 0; mt < 2; mt++) {
        int mA = m0 + mrow0 + mt * 16 + g;
#pragma unroll
        for (int nt = 0; nt < 6; nt++) {
            int n   = ncol0 + nt * 8 + c2;
            int arr = n >> 6, h = n & 63;
            __half* gp = (arr == 0) ? g_k : (arr == 1) ? g_q : g_v;
            *(uint32_t*)&gp[(size_t)mA * H_ + h] = pkh2(acc[mt][nt][0], acc[mt][nt][1]);
            *(uint32_t*)&gp[(size_t)(mA + 8) * H_ + h] = pkh2(acc[mt][nt][2], acc[mt][nt][3]);
        }
    }

    // release: this CTA's 64 rows are visible; tick the batch counter.
    __threadfence();
    __syncthreads();
    if (tid == 0) atomicAdd(&g_rdy[blockIdx.x >> 5], 1);
}

__device__ __forceinline__ void attn_body(float* __restrict__ out, char* smb)
{
    const uint32_t sBase = smem_u32(smb);
    __half* Qs = (__half*)(smb + STAGE_B);   // aliases stage 1

    const int tid  = threadIdx.x;
    const int lane = tid & 31;
    const int warp = tid >> 5;
    const int g    = lane >> 2;
    const int c2   = (lane & 3) * 2;
    const int wrow0 = warp * 16;

    const int ba = blockIdx.x - 256;        // 0..319
    const int b  = ba / 40;                 // batch-major: early CTAs -> batch 0
    const int idx = 39 - (ba % 40);         // big pieces first within batch
    int qb, np, pi;
    if (idx < 4)       { qb = idx;               np = 1; pi = 0; }
    else if (idx < 12) { qb = 4 + (idx - 4) / 2; np = 2; pi = (idx - 4) % 2; }
    else if (idx < 24) { qb = 8 + (idx - 12) / 3; np = 3; pi = (idx - 12) % 3; }
    else               { qb = 12 + (idx - 24) / 4; np = 4; pi = (idx - 24) % 4; }
    const int nb  = 2 * qb + 2;
    const int jlo = pi * nb / np;
    const int jhi = (pi + 1) * nb / np;

    // wait until this batch's q/k/v are projected (32 proj CTAs per batch)
    if (tid == 0) {
        while (atomicAdd(&g_rdy[b], 0) < 32) __nanosleep(128);
    }
    __syncthreads();
    __threadfence();

    // ---- Q tile (128 rows) -> smem -> per-warp register fragments
    const size_t qrow = (size_t)(b * T_ + qb * 128);
    {
        const uint4* q4 = (const uint4*)(g_q + qrow * H_);
#pragma unroll
        for (int kk = 0; kk < 4; kk++) {
            int i2 = tid + 256 * kk;
            int rr = i2 >> 3, seg = i2 & 7;
            *(uint4*)&Qs[rr * AS + seg * 8] = q4[i2];
        }
    }
    __syncthreads();

    uint32_t aQ[4][4];
    {
        const uint32_t sQ = smem_u32(Qs);
#pragma unroll
        for (int ks = 0; ks < 4; ks++) {
            int arow = wrow0 + (lane & 15);
            int acol = ks * 16 + ((lane & 16) >> 1);
            uint32_t off = (uint32_t)(arow * AS + acol) * 2;
            ldsm_x4(aQ[ks][0], aQ[ks][1], aQ[ks][2], aQ[ks][3], sQ + off);
        }
    }
    __syncthreads();

    auto fill_async = [&](int j0, int s) {
        const size_t kr = (size_t)(b * T_ + j0 * 64) * H_;
        const uint32_t st = sBase + s * STAGE_B;
#pragma unroll
        for (int kk = 0; kk < 2; kk++) {
            int i2 = tid + 256 * kk;
            int rr = i2 >> 3, seg = i2 & 7;
            uint32_t doff = (uint32_t)(rr * AS + seg * 8) * 2;
            size_t soff = kr + rr * H_ + seg * 8;
            cp16(st + doff,          g_k + soff);
            cp16(st + COMP_B + doff, g_v + soff);
        }
    };

    float ot[8][4];
#pragma unroll
    for (int t = 0; t < 8; t++)
#pragma unroll
        for (int e = 0; e < 4; e++) ot[t][e] = 0.f;
    uint64_t L0 = 0, L1 = 0;

    const int R0 = qb * 128 + wrow0;

    fill_async(jlo, jlo & 1);
    cp_commit();

    for (int j0 = jlo; j0 < jhi; j0++) {
        cp_wait0();
        __syncthreads();
        if (j0 + 1 < jhi) {
            fill_async(j0 + 1, (j0 + 1) & 1);
            cp_commit();
        }

        const int C0 = j0 * 64;
        if (C0 > R0 + 15) continue;

        const uint32_t st = sBase + (j0 & 1) * STAGE_B;
        const uint32_t sK = st, sV = st + COMP_B;

        // S = Q K^T  (R8 ks-outer form, no inner guards)
        float sc[8][4];
#pragma unroll
        for (int t = 0; t < 8; t++)
#pragma unroll
            for (int e = 0; e < 4; e++) sc[t][e] = 0.f;

#pragma unroll
        for (int ks = 0; ks < 4; ks++) {
#pragma unroll
            for (int p = 0; p < 4; p++) {
                int brow = p * 16 + (lane & 7) + ((lane & 16) >> 1);
                int bcol = ks * 16 + (lane & 8);
                uint32_t boff = (uint32_t)(brow * AS + bcol) * 2;
                uint32_t bh[4];
                ldsm_x4(bh[0], bh[1], bh[2], bh[3], sK + boff);
                mma16816h(sc[2 * p],     aQ[ks][0], aQ[ks][1], aQ[ks][2], aQ[ks][3], bh[0], bh[1]);
                mma16816h(sc[2 * p + 1], aQ[ks][0], aQ[ks][1], aQ[ks][2], aQ[ks][3], bh[2], bh[3]);
            }
        }

        const bool diag = (C0 + 63 > R0);
        const int rowA = R0 + g, rowB = rowA + 8;
#pragma unroll
        for (int ks = 0; ks < 4; ks++) {
            uint64_t PA0 = exp_pair(pk2(sc[2 * ks][0],     sc[2 * ks][1]));
            uint64_t PB0 = exp_pair(pk2(sc[2 * ks][2],     sc[2 * ks][3]));
            uint64_t PA1 = exp_pair(pk2(sc[2 * ks + 1][0], sc[2 * ks + 1][1]));
            uint64_t PB1 = exp_pair(pk2(sc[2 * ks + 1][2], sc[2 * ks + 1][3]));
            if (diag) {
                float a0, a1;
                int col0 = C0 + (2 * ks) * 8 + c2;
                int col1 = col0 + 8;
                upk2(PA0, a0, a1);
                if (col0 > rowA) a0 = 0.f;
                if (col0 + 1 > rowA) a1 = 0.f;
                PA0 = pk2(a0, a1);
                upk2(PB0, a0, a1);
                if (col0 > rowB) a0 = 0.f;
                if (col0 + 1 > rowB) a1 = 0.f;
                PB0 = pk2(a0, a1);
                upk2(PA1, a0, a1);
                if (col1 > rowA) a0 = 0.f;
                if (col1 + 1 > rowA) a1 = 0.f;
                PA1 = pk2(a0, a1);
                upk2(PB1, a0, a1);
                if (col1 > rowB) a0 = 0.f;
                if (col1 + 1 > rowB) a1 = 0.f;
                PB1 = pk2(a0, a1);
            }
            L0 = f2add(L0, f2add(PA0, PA1));
            L1 = f2add(L1, f2add(PB0, PB1));

            uint32_t ph[4];
            ph[0] = pkh2p(PA0);
            ph[1] = pkh2p(PB0);
            ph[2] = pkh2p(PA1);
            ph[3] = pkh2p(PB1);
#pragma unroll
            for (int p = 0; p < 4; p++) {
                int vj = ks * 16 + (lane & 7) + (lane & 8);
                int vh = p * 16 + ((lane & 16) >> 1);
                uint32_t boff = (uint32_t)(vj * AS + vh) * 2;
                uint32_t bh[4];
                ldsm_x4_t(bh[0], bh[1], bh[2], bh[3], sV + boff);
                mma16816h(ot[2 * p],     ph[0], ph[1], ph[2], ph[3], bh[0], bh[1]);
                mma16816h(ot[2 * p + 1], ph[0], ph[1], ph[2], ph[3], bh[2], bh[3]);
            }
        }
    }

    // reduce row sums
    float la, lb, l0, l1;
    upk2(L0, la, lb); l0 = la + lb;
    upk2(L1, la, lb); l1 = la + lb;
    l0 += __shfl_xor_sync(0xffffffffu, l0, 1);
    l0 += __shfl_xor_sync(0xffffffffu, l0, 2);
    l1 += __shfl_xor_sync(0xffffffffu, l1, 1);
    l1 += __shfl_xor_sync(0xffffffffu, l1, 2);

    if (np == 1) {
        float inv0 = 1.0f / l0, inv1 = 1.0f / l1;
        const size_t rA = qrow + wrow0 + g;
        const size_t rB = rA + 8;
#pragma unroll
        for (int nt = 0; nt < 8; nt++) {
            *(float2*)&out[rA * H_ + nt * 8 + c2] =
                make_float2(ot[nt][0] * inv0, ot[nt][1] * inv0);
            *(float2*)&out[rB * H_ + nt * 8 + c2] =
                make_float2(ot[nt][2] * inv1, ot[nt][3] * inv1);
        }
        return;
    }

    // write partials, then tick the (b,qb) counter (release)
    {
        float* po = g_po + ((size_t)(b * 40 + idx) * 8192);
        float* pl = g_pl + ((size_t)(b * 40 + idx) * 128);
        const int rowA = wrow0 + g;
#pragma unroll
        for (int nt = 0; nt < 8; nt++) {
            *(float2*)&po[rowA * 64 + nt * 8 + c2] = make_float2(ot[nt][0], ot[nt][1]);
            *(float2*)&po[(rowA + 8) * 64 + nt * 8 + c2] = make_float2(ot[nt][2], ot[nt][3]);
        }
        if ((lane & 3) == 0) {
            pl[rowA] = l0;
            pl[rowA + 8] = l1;
        }
    }
    __threadfence();
    __syncthreads();
    if (tid == 0) atomicAdd(&g_cnt[b * 16 + qb], 1);
}

__device__ __forceinline__ void combine_body(float* __restrict__ out)
{
    const int cb = blockIdx.x - 576;        // 0..95
    const int b  = cb / 12;
    const int qb = 4 + cb % 12;
    int start, np;
    if (qb < 8)       { start = 4 + 2 * (qb - 4);   np = 2; }
    else if (qb < 12) { start = 12 + 3 * (qb - 8);  np = 3; }
    else              { start = 24 + 4 * (qb - 12); np = 4; }

    const int tid = threadIdx.x;

    if (tid == 0) {
        while (atomicAdd(&g_cnt[b * 16 + qb], 0) < np) __nanosleep(128);
    }
    __syncthreads();
    __threadfence();

    const float* po0 = g_po + ((size_t)(b * 40 + start) * 8192);
    const float* pl0 = g_pl + ((size_t)(b * 40 + start) * 128);

    const int row  = tid >> 1;
    const int hoff = (tid & 1) * 32;

    float l = 0.f;
#pragma unroll 4
    for (int p = 0; p < np; p++) l += pl0[p * 128 + row];
    float inv = 1.0f / l;

    const size_t obase = ((size_t)(b * T_ + qb * 128 + row)) * H_ + hoff;
#pragma unroll
    for (int k = 0; k < 8; k++) {
        float4 a = *(const float4*)&po0[row * 64 + hoff + k * 4];
#pragma unroll 4
        for (int p = 1; p < np; p++) {
            float4 c = *(const float4*)&po0[p * 8192 + row * 64 + hoff + k * 4];
            a.x += c.x; a.y += c.y; a.z += c.z; a.w += c.w;
        }
        *(float4*)&out[obase + k * 4] =
            make_float4(a.x * inv, a.y * inv, a.z * inv, a.w * inv);
    }
}

__global__ __launch_bounds__(256, 2) void fused_kernel(float* __restrict__ out,
                                                       const float* __restrict__ x)
{
    extern __shared__ __align__(16) char smb[];
    if (blockIdx.x < 256)       proj_body(x, smb);
    else if (blockIdx.x < 576)  attn_body(out, smb);
    else                        combine_body(out);
}

// ---------------------------------------------------------------------------
extern "C" void kernel_launch(void* const* d_in, const int* in_sizes, int n_in,
                              void* d_out, int out_size)
{
    const float* x  = (const float*)d_in[0];
    const float* Wk = (const float*)d_in[1];
    const float* Wq = (const float*)d_in[2];
    const float* Wv = (const float*)d_in[3];
    float* out = (float*)d_out;

    convert_w_kernel<<<(NW_ * C_ / 4 + 255) / 256, 256>>>(Wk, Wq, Wv);

    cudaFuncSetAttribute(fused_kernel, cudaFuncAttributeMaxDynamicSharedMemorySize, FUSED_SMEM);
    fused_kernel<<<672, 256, FUSED_SMEM>>>(out, x);
}

// round 13
// speedup vs baseline: 1.1370x; 1.1370x over previous
#include <cuda_runtime.h>
#include <cuda_fp16.h>
#include <cstdint>

#define B_ 8
#define T_ 2048
#define C_ 1024
#define H_ 64
#define NW_ 192

// ---------------------------------------------------------------------------
// Global scratch
// ---------------------------------------------------------------------------
__device__ __half g_w[NW_ * C_];
__device__ __half g_q[B_ * T_ * H_];
__device__ __half g_k[B_ * T_ * H_];
__device__ __half g_v[B_ * T_ * H_];
__device__ float g_po[B_ * 40 * 128 * 64];
__device__ float g_pl[B_ * 40 * 128];
__device__ int   g_tile[B_ * 32];   // per-64-row-region readiness (one per proj CTA)

// ---------------------------------------------------------------------------
// Basic helpers
// ---------------------------------------------------------------------------
__device__ __forceinline__ uint32_t smem_u32(const void* p) {
    return (uint32_t)__cvta_generic_to_shared(p);
}
__device__ __forceinline__ void ldsm_x4(uint32_t& r0, uint32_t& r1,
                                        uint32_t& r2, uint32_t& r3, uint32_t addr) {
    asm volatile("ldmatrix.sync.aligned.m8n8.x4.shared.b16 {%0,%1,%2,%3}, [%4];"
                 : "=r"(r0), "=r"(r1), "=r"(r2), "=r"(r3) : "r"(addr));
}
__device__ __forceinline__ void ldsm_x4_t(uint32_t& r0, uint32_t& r1,
                                          uint32_t& r2, uint32_t& r3, uint32_t addr) {
    asm volatile("ldmatrix.sync.aligned.m8n8.x4.trans.shared.b16 {%0,%1,%2,%3}, [%4];"
                 : "=r"(r0), "=r"(r1), "=r"(r2), "=r"(r3) : "r"(addr));
}
__device__ __forceinline__ void mma16816h(float* d,
                                          uint32_t a0, uint32_t a1, uint32_t a2, uint32_t a3,
                                          uint32_t b0, uint32_t b1) {
    asm volatile("mma.sync.aligned.m16n8k16.row.col.f32.f16.f16.f32 "
                 "{%0,%1,%2,%3}, {%4,%5,%6,%7}, {%8,%9}, {%0,%1,%2,%3};"
                 : "+f"(d[0]), "+f"(d[1]), "+f"(d[2]), "+f"(d[3])
                 : "r"(a0), "r"(a1), "r"(a2), "r"(a3), "r"(b0), "r"(b1));
}
__device__ __forceinline__ void cp16(uint32_t dst, const void* src) {
    asm volatile("cp.async.cg.shared.global [%0], [%1], 16;" :: "r"(dst), "l"(src));
}
__device__ __forceinline__ void cp_commit() { asm volatile("cp.async.commit_group;"); }
__device__ __forceinline__ void cp_wait0()  { asm volatile("cp.async.wait_group 0;"); }

// ---------------------------------------------------------------------------
// Packed f32x2 helpers
// ---------------------------------------------------------------------------
__device__ __forceinline__ uint64_t pk2(float a, float b) {
    uint64_t r; asm("mov.b64 %0, {%1, %2};" : "=l"(r) : "f"(a), "f"(b)); return r;
}
__device__ __forceinline__ void upk2(uint64_t v, float& a, float& b) {
    asm("mov.b64 {%0, %1}, %2;" : "=f"(a), "=f"(b) : "l"(v));
}
__device__ __forceinline__ uint64_t pk2u(uint32_t a, uint32_t b) {
    uint64_t r; asm("mov.b64 %0, {%1, %2};" : "=l"(r) : "r"(a), "r"(b)); return r;
}
__device__ __forceinline__ void upk2u(uint64_t v, uint32_t& a, uint32_t& b) {
    asm("mov.b64 {%0, %1}, %2;" : "=r"(a), "=r"(b) : "l"(v));
}
__device__ __forceinline__ uint64_t f2mul(uint64_t a, uint64_t b) {
    uint64_t d; asm("mul.rn.f32x2 %0, %1, %2;" : "=l"(d) : "l"(a), "l"(b)); return d;
}
__device__ __forceinline__ uint64_t f2add(uint64_t a, uint64_t b) {
    uint64_t d; asm("add.rn.f32x2 %0, %1, %2;" : "=l"(d) : "l"(a), "l"(b)); return d;
}
__device__ __forceinline__ uint64_t f2fma(uint64_t a, uint64_t b, uint64_t c) {
    uint64_t d; asm("fma.rn.f32x2 %0, %1, %2, %3;" : "=l"(d) : "l"(a), "l"(b), "l"(c)); return d;
}
#define DUP2(x) (0x100000001ULL * (uint64_t)__float_as_uint(x))

__device__ __forceinline__ uint64_t exp_pair(uint64_t S2) {
    uint64_t Y2 = f2mul(S2, DUP2(0.045084220027780105f));
    uint64_t Z2 = f2add(Y2, DUP2(12582912.0f));
    uint64_t R2 = f2add(Z2, DUP2(-12582912.0f));
    uint64_t F2 = f2fma(R2, DUP2(-1.0f), Y2);
    uint64_t P2 = f2fma(DUP2(1.3333558e-3f), F2, DUP2(9.6181291e-3f));
    P2 = f2fma(P2, F2, DUP2(5.5504109e-2f));
    P2 = f2fma(P2, F2, DUP2(2.4022651e-1f));
    P2 = f2fma(P2, F2, DUP2(6.9314718e-1f));
    P2 = f2fma(P2, F2, DUP2(1.0f));
    uint32_t z0, z1; upk2u(Z2, z0, z1);
    uint32_t s0 = (z0 + 0xB4C0007Fu) << 23;
    uint32_t s1 = (z1 + 0xB4C0007Fu) << 23;
    return f2mul(P2, pk2u(s0, s1));
}

__device__ __forceinline__ uint32_t pkh2(float a, float b) {
    uint32_t r; asm("cvt.rn.f16x2.f32 %0, %1, %2;" : "=r"(r) : "f"(b), "f"(a)); return r;
}
__device__ __forceinline__ uint32_t pkh2p(uint64_t v2) {
    float a, b; upk2(v2, a, b);
    return pkh2(a, b);
}

// ---------------------------------------------------------------------------
// Kernel 1: weights -> fp16 (vectorized) + reset region flags.
// ---------------------------------------------------------------------------
__global__ __launch_bounds__(256) void convert_w_kernel(const float* __restrict__ Wk,
                                                        const float* __restrict__ Wq,
                                                        const float* __restrict__ Wv) {
    if (blockIdx.x == 0 && threadIdx.x < B_ * 32) g_tile[threadIdx.x] = 0;
    int i4 = blockIdx.x * 256 + threadIdx.x;
    if (i4 >= NW_ * C_ / 4) return;
    int idx = i4 * 4;
    int n = idx >> 10, c = idx & 1023;
    const float* src = (n < 64) ? Wk : (n < 128) ? Wq : Wv;
    float4 v = *(const float4*)(src + (n & 63) * C_ + c);
    *(uint2*)&g_w[idx] = make_uint2(pkh2(v.x, v.y), pkh2(v.z, v.w));
}

// ---------------------------------------------------------------------------
// Fused proj (bids 0..255) + attn (bids 256..575) with per-region tickets.
// Bodies are exactly the round-8 champion code; only tickets added.
// ---------------------------------------------------------------------------
#define XP 24
#define PX_ST (64 * XP * 2)        // 3072
#define PW_ST (NW_ * XP * 2)       // 9216
#define AS 72
#define COMP_B (64 * AS * 2)       // 9216
#define STAGE_B (2 * COMP_B)       // 18432 (K + V)
#define FUSED_SMEM (2 * STAGE_B)   // 36864 (proj needs 24576)

__device__ __forceinline__ void proj_body(const float* __restrict__ x, char* psm)
{
    __half* Xs[2] = {(__half*)psm, (__half*)(psm + PX_ST)};
    __half* Ws[2] = {(__half*)(psm + 2 * PX_ST), (__half*)(psm + 2 * PX_ST + PW_ST)};

    const int tid  = threadIdx.x;
    const int lane = tid & 31;
    const int warp = tid >> 5;
    const int m0    = blockIdx.x * 64;
    const int mrow0 = (warp >> 2) * 32;
    const int ncol0 = (warp & 3) * 48;

    const int xr = tid >> 2;
    const int xc = (tid & 3) * 4;

    float acc[2][6][4];
#pragma unroll
    for (int mt = 0; mt < 2; mt++)
#pragma unroll
        for (int nt = 0; nt < 6; nt++)
#pragma unroll
            for (int e = 0; e < 4; e++) acc[mt][nt][e] = 0.f;

    auto issue_w = [&](int kb, int s) {
#pragma unroll
        for (int rr = 0; rr < 2; rr++) {
            int c = tid + 256 * rr;
            if (c < 384) {
                int n = c >> 1, half = c & 1;
                const __half* src = g_w + (size_t)n * C_ + kb * 16 + half * 8;
                cp16(smem_u32(Ws[s] + n * XP + half * 8), src);
            }
        }
    };

    float4 nx;
    auto load_x = [&](int kb) {
        nx = *(const float4*)(x + (size_t)(m0 + xr) * C_ + kb * 16 + xc);
    };
    auto store_x = [&](int s) {
        uint32_t h01 = pkh2(nx.x, nx.y);
        uint32_t h23 = pkh2(nx.z, nx.w);
        asm volatile("st.shared.v2.b32 [%0], {%1,%2};"
                     :: "r"(smem_u32(&Xs[s][xr * XP + xc])), "r"(h01), "r"(h23));
    };

    issue_w(0, 0);
    cp_commit();
    load_x(0);
    store_x(0);
    cp_wait0();
    __syncthreads();

    for (int kb = 0; kb < 64; kb++) {
        const int s = kb & 1;
        if (kb < 63) {
            issue_w(kb + 1, s ^ 1);
            cp_commit();
            load_x(kb + 1);
        }

        const uint32_t sX = smem_u32(Xs[s]);
        const uint32_t sW = smem_u32(Ws[s]);

        uint32_t bh[6][2];
#pragma unroll
        for (int p = 0; p < 3; p++) {
            int brow = ncol0 + p * 16 + (lane & 7) + ((lane & 16) >> 1);
            int bcol = (lane & 8);
            uint32_t off = (uint32_t)(brow * XP + bcol) * 2;
            ldsm_x4(bh[2 * p][0], bh[2 * p][1], bh[2 * p + 1][0], bh[2 * p + 1][1], sW + off);
        }
#pragma unroll
        for (int mt = 0; mt < 2; mt++) {
            int arow = mrow0 + mt * 16 + (lane & 15);
            int acol = ((lane & 16) >> 1);
            uint32_t off = (uint32_t)(arow * XP + acol) * 2;
            uint32_t a[4];
            ldsm_x4(a[0], a[1], a[2], a[3], sX + off);
#pragma unroll
            for (int nt = 0; nt < 6; nt++)
                mma16816h(acc[mt][nt], a[0], a[1], a[2], a[3], bh[nt][0], bh[nt][1]);
        }
        if (kb < 63) store_x(s ^ 1);
        cp_wait0();
        __syncthreads();
    }

    const int g  = lane >> 2;
    const int c2 = (lane & 3) * 2;
#pragma unroll
    for (int mt = 0; mt < 2; mt++) {
        int mA = m0 + mrow0 + mt * 16 + g;
#pragma unroll
        for (int nt = 0; nt < 6; nt++) {
            int n   = ncol0 + nt * 8 + c2;
            int arr = n >> 6, h = n & 63;
            __half* gp = (arr == 0) ? g_k : (arr == 1) ? g_q : g_v;
            *(uint32_t*)&gp[(size_t)mA * H_ + h] = pkh2(acc[mt][nt][0], acc[mt][nt][1]);
            *(uint32_t*)&gp[(size_t)(mA + 8) * H_ + h] = pkh2(acc[mt][nt][2], acc[mt][nt][3]);
        }
    }

    // release this 64-row region
    __threadfence();
    __syncthreads();
    if (tid == 0) atomicExch(&g_tile[blockIdx.x], 1);
}

__device__ __forceinline__ void attn_body(float* __restrict__ out, char* smb)
{
    const uint32_t sBase = smem_u32(smb);
    __half* Qs = (__half*)(smb + STAGE_B);   // aliases stage 1

    const int tid  = threadIdx.x;
    const int lane = tid & 31;
    const int warp = tid >> 5;
    const int g    = lane >> 2;
    const int c2   = (lane & 3) * 2;
    const int wrow0 = warp * 16;

    const int u = blockIdx.x - 256;         // 0..319
    const int b = u & 7;
    const int idx = 39 - (u >> 3);          // reversed: big pieces first
    int qb, np, pi;
    if (idx < 4)       { qb = idx;               np = 1; pi = 0; }
    else if (idx < 12) { qb = 4 + (idx - 4) / 2; np = 2; pi = (idx - 4) % 2; }
    else if (idx < 24) { qb = 8 + (idx - 12) / 3; np = 3; pi = (idx - 12) % 3; }
    else               { qb = 12 + (idx - 24) / 4; np = 4; pi = (idx - 24) % 4; }
    const int nb  = 2 * qb + 2;
    const int jlo = pi * nb / np;
    const int jhi = (pi + 1) * nb / np;

    auto wait_tile = [&](int t) {   // region t of batch b (64 rows)
        if (tid == 0) {
            while (atomicAdd(&g_tile[b * 32 + t], 0) == 0) __nanosleep(64);
        }
        __syncthreads();
    };

    // ---- wait for Q regions, then load Q tile -> smem -> register fragments
    wait_tile(2 * qb);
    wait_tile(2 * qb + 1);
    const size_t qrow = (size_t)(b * T_ + qb * 128);
    {
        const uint4* q4 = (const uint4*)(g_q + qrow * H_);
#pragma unroll
        for (int kk = 0; kk < 4; kk++) {
            int i2 = tid + 256 * kk;
            int rr = i2 >> 3, seg = i2 & 7;
            *(uint4*)&Qs[rr * AS + seg * 8] = q4[i2];
        }
    }
    __syncthreads();

    uint32_t aQ[4][4];
    {
        const uint32_t sQ = smem_u32(Qs);
#pragma unroll
        for (int ks = 0; ks < 4; ks++) {
            int arow = wrow0 + (lane & 15);
            int acol = ks * 16 + ((lane & 16) >> 1);
            uint32_t off = (uint32_t)(arow * AS + acol) * 2;
            ldsm_x4(aQ[ks][0], aQ[ks][1], aQ[ks][2], aQ[ks][3], sQ + off);
        }
    }
    __syncthreads();

    auto fill_async = [&](int j0, int s) {
        const size_t kr = (size_t)(b * T_ + j0 * 64) * H_;
        const uint32_t st = sBase + s * STAGE_B;
#pragma unroll
        for (int kk = 0; kk < 2; kk++) {
            int i2 = tid + 256 * kk;
            int rr = i2 >> 3, seg = i2 & 7;
            uint32_t doff = (uint32_t)(rr * AS + seg * 8) * 2;
            size_t soff = kr + rr * H_ + seg * 8;
            cp16(st + doff,          g_k + soff);
            cp16(st + COMP_B + doff, g_v + soff);
        }
    };

    float ot[8][4];
#pragma unroll
    for (int t = 0; t < 8; t++)
#pragma unroll
        for (int e = 0; e < 4; e++) ot[t][e] = 0.f;
    uint64_t L0 = 0, L1 = 0;

    const int R0 = qb * 128 + wrow0;

    wait_tile(jlo);
    fill_async(jlo, jlo & 1);
    cp_commit();

    for (int j0 = jlo; j0 < jhi; j0++) {
        cp_wait0();
        __syncthreads();
        if (j0 + 1 < jhi) {
            wait_tile(j0 + 1);
            fill_async(j0 + 1, (j0 + 1) & 1);
            cp_commit();
        }

        const int C0 = j0 * 64;
        if (C0 > R0 + 15) continue;

        const uint32_t st = sBase + (j0 & 1) * STAGE_B;
        const uint32_t sK = st, sV = st + COMP_B;

        // S = Q K^T (R8 ks-outer form)
        float sc[8][4];
#pragma unroll
        for (int t = 0; t < 8; t++)
#pragma unroll
            for (int e = 0; e < 4; e++) sc[t][e] = 0.f;

#pragma unroll
        for (int ks = 0; ks < 4; ks++) {
#pragma unroll
            for (int p = 0; p < 4; p++) {
                int brow = p * 16 + (lane & 7) + ((lane & 16) >> 1);
                int bcol = ks * 16 + (lane & 8);
                uint32_t boff = (uint32_t)(brow * AS + bcol) * 2;
                uint32_t bh[4];
                ldsm_x4(bh[0], bh[1], bh[2], bh[3], sK + boff);
                mma16816h(sc[2 * p],     aQ[ks][0], aQ[ks][1], aQ[ks][2], aQ[ks][3], bh[0], bh[1]);
                mma16816h(sc[2 * p + 1], aQ[ks][0], aQ[ks][1], aQ[ks][2], aQ[ks][3], bh[2], bh[3]);
            }
        }

        const bool diag = (C0 + 63 > R0);
        const int rowA = R0 + g, rowB = rowA + 8;
#pragma unroll
        for (int ks = 0; ks < 4; ks++) {
            uint64_t PA0 = exp_pair(pk2(sc[2 * ks][0],     sc[2 * ks][1]));
            uint64_t PB0 = exp_pair(pk2(sc[2 * ks][2],     sc[2 * ks][3]));
            uint64_t PA1 = exp_pair(pk2(sc[2 * ks + 1][0], sc[2 * ks + 1][1]));
            uint64_t PB1 = exp_pair(pk2(sc[2 * ks + 1][2], sc[2 * ks + 1][3]));
            if (diag) {
                float a0, a1;
                int col0 = C0 + (2 * ks) * 8 + c2;
                int col1 = col0 + 8;
                upk2(PA0, a0, a1);
                if (col0 > rowA) a0 = 0.f;
                if (col0 + 1 > rowA) a1 = 0.f;
                PA0 = pk2(a0, a1);
                upk2(PB0, a0, a1);
                if (col0 > rowB) a0 = 0.f;
                if (col0 + 1 > rowB) a1 = 0.f;
                PB0 = pk2(a0, a1);
                upk2(PA1, a0, a1);
                if (col1 > rowA) a0 = 0.f;
                if (col1 + 1 > rowA) a1 = 0.f;
                PA1 = pk2(a0, a1);
                upk2(PB1, a0, a1);
                if (col1 > rowB) a0 = 0.f;
                if (col1 + 1 > rowB) a1 = 0.f;
                PB1 = pk2(a0, a1);
            }
            L0 = f2add(L0, f2add(PA0, PA1));
            L1 = f2add(L1, f2add(PB0, PB1));

            uint32_t ph[4];
            ph[0] = pkh2p(PA0);
            ph[1] = pkh2p(PB0);
            ph[2] = pkh2p(PA1);
            ph[3] = pkh2p(PB1);
#pragma unroll
            for (int p = 0; p < 4; p++) {
                int vj = ks * 16 + (lane & 7) + (lane & 8);
                int vh = p * 16 + ((lane & 16) >> 1);
                uint32_t boff = (uint32_t)(vj * AS + vh) * 2;
                uint32_t bh[4];
                ldsm_x4_t(bh[0], bh[1], bh[2], bh[3], sV + boff);
                mma16816h(ot[2 * p],     ph[0], ph[1], ph[2], ph[3], bh[0], bh[1]);
                mma16816h(ot[2 * p + 1], ph[0], ph[1], ph[2], ph[3], bh[2], bh[3]);
            }
        }
    }

    // reduce row sums
    float la, lb, l0, l1;
    upk2(L0, la, lb); l0 = la + lb;
    upk2(L1, la, lb); l1 = la + lb;
    l0 += __shfl_xor_sync(0xffffffffu, l0, 1);
    l0 += __shfl_xor_sync(0xffffffffu, l0, 2);
    l1 += __shfl_xor_sync(0xffffffffu, l1, 1);
    l1 += __shfl_xor_sync(0xffffffffu, l1, 2);

    if (np == 1) {
        float inv0 = 1.0f / l0, inv1 = 1.0f / l1;
        const size_t rA = qrow + wrow0 + g;
        const size_t rB = rA + 8;
#pragma unroll
        for (int nt = 0; nt < 8; nt++) {
            *(float2*)&out[rA * H_ + nt * 8 + c2] =
                make_float2(ot[nt][0] * inv0, ot[nt][1] * inv0);
            *(float2*)&out[rB * H_ + nt * 8 + c2] =
                make_float2(ot[nt][2] * inv1, ot[nt][3] * inv1);
        }
        return;
    }

    // write partials (combine kernel normalizes after kernel boundary)
    float* po = g_po + ((size_t)(b * 40 + idx) * 8192);
    float* pl = g_pl + ((size_t)(b * 40 + idx) * 128);
    const int rowA = wrow0 + g;
#pragma unroll
    for (int nt = 0; nt < 8; nt++) {
        *(float2*)&po[rowA * 64 + nt * 8 + c2] = make_float2(ot[nt][0], ot[nt][1]);
        *(float2*)&po[(rowA + 8) * 64 + nt * 8 + c2] = make_float2(ot[nt][2], ot[nt][3]);
    }
    if ((lane & 3) == 0) {
        pl[rowA] = l0;
        pl[rowA + 8] = l1;
    }
}

__global__ __launch_bounds__(256, 2) void fused_kernel(float* __restrict__ out,
                                                       const float* __restrict__ x)
{
    extern __shared__ __align__(16) char smb[];
    if (blockIdx.x < 256) proj_body(x, smb);
    else                  attn_body(out, smb);
}

// ---------------------------------------------------------------------------
// Kernel 3: combine pieces + normalize for qb >= 4 (R8 version).
// grid = B * 12 * 4 (row quarters), 128 threads.
// ---------------------------------------------------------------------------
__global__ __launch_bounds__(128) void combine_kernel(float* __restrict__ out)
{
    const int u  = blockIdx.x;
    const int b  = u / 48;
    const int rem = u % 48;
    const int qb = 4 + (rem >> 2);
    const int quarter = rem & 3;
    int start, np;
    if (qb < 8)       { start = 4 + 2 * (qb - 4);   np = 2; }
    else if (qb < 12) { start = 12 + 3 * (qb - 8);  np = 3; }
    else              { start = 24 + 4 * (qb - 12); np = 4; }

    const int tid = threadIdx.x;
    const int row = quarter * 32 + (tid >> 2);
    const int quad = tid & 3;

    const float* po = g_po + ((size_t)(b * 40 + start) * 8192);
    const float* pl = g_pl + ((size_t)(b * 40 + start) * 128);

    float l = 0.f;
#pragma unroll 4
    for (int p = 0; p < np; p++) l += pl[p * 128 + row];
    float inv = 1.0f / l;

    const size_t obase = ((size_t)(b * T_ + qb * 128 + row)) * H_;
#pragma unroll
    for (int k = 0; k < 4; k++) {
        int col = quad * 16 + k * 4;
        float4 a = *(const float4*)&po[row * 64 + col];
#pragma unroll 4
        for (int p = 1; p < np; p++) {
            float4 c = *(const float4*)&po[p * 8192 + row * 64 + col];
            a.x += c.x; a.y += c.y; a.z += c.z; a.w += c.w;
        }
        *(float4*)&out[obase + col] =
            make_float4(a.x * inv, a.y * inv, a.z * inv, a.w * inv);
    }
}

// ---------------------------------------------------------------------------
extern "C" void kernel_launch(void* const* d_in, const int* in_sizes, int n_in,
                              void* d_out, int out_size)
{
    const float* x  = (const float*)d_in[0];
    const float* Wk = (const float*)d_in[1];
    const float* Wq = (const float*)d_in[2];
    const float* Wv = (const float*)d_in[3];
    float* out = (float*)d_out;

    convert_w_kernel<<<(NW_ * C_ / 4 + 255) / 256, 256>>>(Wk, Wq, Wv);

    cudaFuncSetAttribute(fused_kernel, cudaFuncAttributeMaxDynamicSharedMemorySize, FUSED_SMEM);
    fused_kernel<<<576, 256, FUSED_SMEM>>>(out, x);

    combine_kernel<<<B_ * 12 * 4, 128>>>(out);
}

// round 14
// speedup vs baseline: 1.1414x; 1.0039x over previous
#include <cuda_runtime.h>
#include <cuda_fp16.h>
#include <cstdint>

#define B_ 8
#define T_ 2048
#define C_ 1024
#define H_ 64
#define NW_ 192

// ---------------------------------------------------------------------------
// Global scratch (all counters self-zeroing across graph replays)
// ---------------------------------------------------------------------------
__device__ __half g_w[NW_ * C_];
__device__ __half g_q[B_ * T_ * H_];
__device__ __half g_k[B_ * T_ * H_];
__device__ __half g_v[B_ * T_ * H_];
__device__ float g_po[B_ * 40 * 128 * 64];
__device__ float g_pl[B_ * 40 * 128];
__device__ int   g_tile[B_ * 32];   // counting semaphores, return to 0 each launch
__device__ int   g_wflag;           // low 16 bits: converters done; high: proj passers

// ---------------------------------------------------------------------------
// Basic helpers
// ---------------------------------------------------------------------------
__device__ __forceinline__ uint32_t smem_u32(const void* p) {
    return (uint32_t)__cvta_generic_to_shared(p);
}
__device__ __forceinline__ void ldsm_x4(uint32_t& r0, uint32_t& r1,
                                        uint32_t& r2, uint32_t& r3, uint32_t addr) {
    asm volatile("ldmatrix.sync.aligned.m8n8.x4.shared.b16 {%0,%1,%2,%3}, [%4];"
                 : "=r"(r0), "=r"(r1), "=r"(r2), "=r"(r3) : "r"(addr));
}
__device__ __forceinline__ void ldsm_x4_t(uint32_t& r0, uint32_t& r1,
                                          uint32_t& r2, uint32_t& r3, uint32_t addr) {
    asm volatile("ldmatrix.sync.aligned.m8n8.x4.trans.shared.b16 {%0,%1,%2,%3}, [%4];"
                 : "=r"(r0), "=r"(r1), "=r"(r2), "=r"(r3) : "r"(addr));
}
__device__ __forceinline__ void mma16816h(float* d,
                                          uint32_t a0, uint32_t a1, uint32_t a2, uint32_t a3,
                                          uint32_t b0, uint32_t b1) {
    asm volatile("mma.sync.aligned.m16n8k16.row.col.f32.f16.f16.f32 "
                 "{%0,%1,%2,%3}, {%4,%5,%6,%7}, {%8,%9}, {%0,%1,%2,%3};"
                 : "+f"(d[0]), "+f"(d[1]), "+f"(d[2]), "+f"(d[3])
                 : "r"(a0), "r"(a1), "r"(a2), "r"(a3), "r"(b0), "r"(b1));
}
__device__ __forceinline__ void cp16(uint32_t dst, const void* src) {
    asm volatile("cp.async.cg.shared.global [%0], [%1], 16;" :: "r"(dst), "l"(src));
}
__device__ __forceinline__ void cp_commit() { asm volatile("cp.async.commit_group;"); }
__device__ __forceinline__ void cp_wait0()  { asm volatile("cp.async.wait_group 0;"); }

// ---------------------------------------------------------------------------
// Packed f32x2 helpers
// ---------------------------------------------------------------------------
__device__ __forceinline__ uint64_t pk2(float a, float b) {
    uint64_t r; asm("mov.b64 %0, {%1, %2};" : "=l"(r) : "f"(a), "f"(b)); return r;
}
__device__ __forceinline__ void upk2(uint64_t v, float& a, float& b) {
    asm("mov.b64 {%0, %1}, %2;" : "=f"(a), "=f"(b) : "l"(v));
}
__device__ __forceinline__ uint64_t pk2u(uint32_t a, uint32_t b) {
    uint64_t r; asm("mov.b64 %0, {%1, %2};" : "=l"(r) : "r"(a), "r"(b)); return r;
}
__device__ __forceinline__ void upk2u(uint64_t v, uint32_t& a, uint32_t& b) {
    asm("mov.b64 {%0, %1}, %2;" : "=r"(a), "=r"(b) : "l"(v));
}
__device__ __forceinline__ uint64_t f2mul(uint64_t a, uint64_t b) {
    uint64_t d; asm("mul.rn.f32x2 %0, %1, %2;" : "=l"(d) : "l"(a), "l"(b)); return d;
}
__device__ __forceinline__ uint64_t f2add(uint64_t a, uint64_t b) {
    uint64_t d; asm("add.rn.f32x2 %0, %1, %2;" : "=l"(d) : "l"(a), "l"(b)); return d;
}
__device__ __forceinline__ uint64_t f2fma(uint64_t a, uint64_t b, uint64_t c) {
    uint64_t d; asm("fma.rn.f32x2 %0, %1, %2, %3;" : "=l"(d) : "l"(a), "l"(b), "l"(c)); return d;
}
#define DUP2(x) (0x100000001ULL * (uint64_t)__float_as_uint(x))

__device__ __forceinline__ uint64_t exp_pair(uint64_t S2) {
    uint64_t Y2 = f2mul(S2, DUP2(0.045084220027780105f));
    uint64_t Z2 = f2add(Y2, DUP2(12582912.0f));
    uint64_t R2 = f2add(Z2, DUP2(-12582912.0f));
    uint64_t F2 = f2fma(R2, DUP2(-1.0f), Y2);
    uint64_t P2 = f2fma(DUP2(1.3333558e-3f), F2, DUP2(9.6181291e-3f));
    P2 = f2fma(P2, F2, DUP2(5.5504109e-2f));
    P2 = f2fma(P2, F2, DUP2(2.4022651e-1f));
    P2 = f2fma(P2, F2, DUP2(6.9314718e-1f));
    P2 = f2fma(P2, F2, DUP2(1.0f));
    uint32_t z0, z1; upk2u(Z2, z0, z1);
    uint32_t s0 = (z0 + 0xB4C0007Fu) << 23;
    uint32_t s1 = (z1 + 0xB4C0007Fu) << 23;
    return f2mul(P2, pk2u(s0, s1));
}

__device__ __forceinline__ uint32_t pkh2(float a, float b) {
    uint32_t r; asm("cvt.rn.f16x2.f32 %0, %1, %2;" : "=r"(r) : "f"(b), "f"(a)); return r;
}
__device__ __forceinline__ uint32_t pkh2p(uint64_t v2) {
    float a, b; upk2(v2, a, b);
    return pkh2(a, b);
}

// ---------------------------------------------------------------------------
// Fused kernel: W-convert (bids 0..15) | proj (16..271) | attn (272..591).
// ---------------------------------------------------------------------------
#define XP 24
#define PX_ST (64 * XP * 2)        // 3072
#define PW_ST (NW_ * XP * 2)       // 9216
#define AS 72
#define COMP_B (64 * AS * 2)       // 9216
#define STAGE_B (2 * COMP_B)       // 18432 (K + V)
#define FUSED_SMEM (2 * STAGE_B)   // 36864

__device__ __forceinline__ void wconv_body(const float* __restrict__ Wk,
                                           const float* __restrict__ Wq,
                                           const float* __restrict__ Wv)
{
    // CTA c converts float4 range [c*3072, (c+1)*3072): 12 per thread.
    const int base = blockIdx.x * 3072 + threadIdx.x;
#pragma unroll
    for (int r = 0; r < 12; r++) {
        int i4 = base + 256 * r;
        int idx = i4 * 4;
        int n = idx >> 10, c = idx & 1023;
        const float* src = (n < 64) ? Wk : (n < 128) ? Wq : Wv;
        float4 v = *(const float4*)(src + (n & 63) * C_ + c);
        *(uint2*)&g_w[idx] = make_uint2(pkh2(v.x, v.y), pkh2(v.z, v.w));
    }
    __threadfence();
    __syncthreads();
    if (threadIdx.x == 0) atomicAdd(&g_wflag, 1);   // producer count (low bits)
}

__device__ __forceinline__ void proj_body(const float* __restrict__ x, char* psm)
{
    __half* Xs[2] = {(__half*)psm, (__half*)(psm + PX_ST)};
    __half* Ws[2] = {(__half*)(psm + 2 * PX_ST), (__half*)(psm + 2 * PX_ST + PW_ST)};

    const int tid  = threadIdx.x;
    const int lane = tid & 31;
    const int warp = tid >> 5;
    const int pb   = blockIdx.x - 16;       // 0..255
    const int m0    = pb * 64;
    const int mrow0 = (warp >> 2) * 32;
    const int ncol0 = (warp & 3) * 48;

    const int xr = tid >> 2;
    const int xc = (tid & 3) * 4;

    float acc[2][6][4];
#pragma unroll
    for (int mt = 0; mt < 2; mt++)
#pragma unroll
        for (int nt = 0; nt < 6; nt++)
#pragma unroll
            for (int e = 0; e < 4; e++) acc[mt][nt][e] = 0.f;

    auto issue_w = [&](int kb, int s) {
#pragma unroll
        for (int rr = 0; rr < 2; rr++) {
            int c = tid + 256 * rr;
            if (c < 384) {
                int n = c >> 1, half = c & 1;
                const __half* src = g_w + (size_t)n * C_ + kb * 16 + half * 8;
                cp16(smem_u32(Ws[s] + n * XP + half * 8), src);
            }
        }
    };

    float4 nx;
    auto load_x = [&](int kb) {
        nx = *(const float4*)(x + (size_t)(m0 + xr) * C_ + kb * 16 + xc);
    };
    auto store_x = [&](int s) {
        uint32_t h01 = pkh2(nx.x, nx.y);
        uint32_t h23 = pkh2(nx.z, nx.w);
        asm volatile("st.shared.v2.b32 [%0], {%1,%2};"
                     :: "r"(smem_u32(&Xs[s][xr * XP + xc])), "r"(h01), "r"(h23));
    };

    // overlap first x tile with the W-wait
    load_x(0);
    store_x(0);

    // wait for all 16 converters; self-zeroing two-field counter.
    if (tid == 0) {
        while ((atomicAdd(&g_wflag, 0) & 0xFFFF) < 16) __nanosleep(64);
        int old = atomicAdd(&g_wflag, 0x10000);
        if ((old >> 16) == 255)                      // 256th passer resets
            atomicSub(&g_wflag, 16 + 256 * 0x10000);
    }
    __syncthreads();
    __threadfence();

    issue_w(0, 0);
    cp_commit();
    cp_wait0();
    __syncthreads();

    for (int kb = 0; kb < 64; kb++) {
        const int s = kb & 1;
        if (kb < 63) {
            issue_w(kb + 1, s ^ 1);
            cp_commit();
            load_x(kb + 1);
        }

        const uint32_t sX = smem_u32(Xs[s]);
        const uint32_t sW = smem_u32(Ws[s]);

        uint32_t bh[6][2];
#pragma unroll
        for (int p = 0; p < 3; p++) {
            int brow = ncol0 + p * 16 + (lane & 7) + ((lane & 16) >> 1);
            int bcol = (lane & 8);
            uint32_t off = (uint32_t)(brow * XP + bcol) * 2;
            ldsm_x4(bh[2 * p][0], bh[2 * p][1], bh[2 * p + 1][0], bh[2 * p + 1][1], sW + off);
        }
#pragma unroll
        for (int mt = 0; mt < 2; mt++) {
            int arow = mrow0 + mt * 16 + (lane & 15);
            int acol = ((lane & 16) >> 1);
            uint32_t off = (uint32_t)(arow * XP + acol) * 2;
            uint32_t a[4];
            ldsm_x4(a[0], a[1], a[2], a[3], sX + off);
#pragma unroll
            for (int nt = 0; nt < 6; nt++)
                mma16816h(acc[mt][nt], a[0], a[1], a[2], a[3], bh[nt][0], bh[nt][1]);
        }
        if (kb < 63) store_x(s ^ 1);
        cp_wait0();
        __syncthreads();
    }

    const int g  = lane >> 2;
    const int c2 = (lane & 3) * 2;
#pragma unroll
    for (int mt = 0; mt < 2; mt++) {
        int mA = m0 + mrow0 + mt * 16 + g;
#pragma unroll
        for (int nt = 0; nt < 6; nt++) {
            int n   = ncol0 + nt * 8 + c2;
            int arr = n >> 6, h = n & 63;
            __half* gp = (arr == 0) ? g_k : (arr == 1) ? g_q : g_v;
            *(uint32_t*)&gp[(size_t)mA * H_ + h] = pkh2(acc[mt][nt][0], acc[mt][nt][1]);
            *(uint32_t*)&gp[(size_t)(mA + 8) * H_ + h] = pkh2(acc[mt][nt][2], acc[mt][nt][3]);
        }
    }

    // release region: add exact waiter count so the flag returns to 0.
    __threadfence();
    __syncthreads();
    if (tid == 0) {
        const int t = pb & 31;
        const int qt = t >> 1;
        const int np_t = (qt < 4) ? 1 : (qt < 8) ? 2 : (qt < 12) ? 3 : 4;
        const int waiters = (16 - qt) + np_t;
        atomicAdd(&g_tile[pb], waiters);
    }
}

__device__ __forceinline__ void attn_body(float* __restrict__ out, char* smb)
{
    const uint32_t sBase = smem_u32(smb);
    __half* Qs = (__half*)(smb + STAGE_B);   // aliases stage 1

    const int tid  = threadIdx.x;
    const int lane = tid & 31;
    const int warp = tid >> 5;
    const int g    = lane >> 2;
    const int c2   = (lane & 3) * 2;
    const int wrow0 = warp * 16;

    const int u = blockIdx.x - 272;         // 0..319
    const int b = u & 7;
    const int idx = 39 - (u >> 3);          // reversed: big pieces first
    int qb, np, pi;
    if (idx < 4)       { qb = idx;               np = 1; pi = 0; }
    else if (idx < 12) { qb = 4 + (idx - 4) / 2; np = 2; pi = (idx - 4) % 2; }
    else if (idx < 24) { qb = 8 + (idx - 12) / 3; np = 3; pi = (idx - 12) % 3; }
    else               { qb = 12 + (idx - 24) / 4; np = 4; pi = (idx - 24) % 4; }
    const int nb  = 2 * qb + 2;
    const int jlo = pi * nb / np;
    const int jhi = (pi + 1) * nb / np;

    auto wait_tile = [&](int t) {   // acquire + consume one count
        if (tid == 0) {
            while (atomicAdd(&g_tile[b * 32 + t], 0) <= 0) __nanosleep(64);
            atomicSub(&g_tile[b * 32 + t], 1);
        }
        __syncthreads();
    };

    // ---- wait for Q regions, then load Q tile -> smem -> register fragments
    wait_tile(2 * qb);
    wait_tile(2 * qb + 1);
    const size_t qrow = (size_t)(b * T_ + qb * 128);
    {
        const uint4* q4 = (const uint4*)(g_q + qrow * H_);
#pragma unroll
        for (int kk = 0; kk < 4; kk++) {
            int i2 = tid + 256 * kk;
            int rr = i2 >> 3, seg = i2 & 7;
            *(uint4*)&Qs[rr * AS + seg * 8] = q4[i2];
        }
    }
    __syncthreads();

    uint32_t aQ[4][4];
    {
        const uint32_t sQ = smem_u32(Qs);
#pragma unroll
        for (int ks = 0; ks < 4; ks++) {
            int arow = wrow0 + (lane & 15);
            int acol = ks * 16 + ((lane & 16) >> 1);
            uint32_t off = (uint32_t)(arow * AS + acol) * 2;
            ldsm_x4(aQ[ks][0], aQ[ks][1], aQ[ks][2], aQ[ks][3], sQ + off);
        }
    }
    __syncthreads();

    auto fill_async = [&](int j0, int s) {
        const size_t kr = (size_t)(b * T_ + j0 * 64) * H_;
        const uint32_t st = sBase + s * STAGE_B;
#pragma unroll
        for (int kk = 0; kk < 2; kk++) {
            int i2 = tid + 256 * kk;
            int rr = i2 >> 3, seg = i2 & 7;
            uint32_t doff = (uint32_t)(rr * AS + seg * 8) * 2;
            size_t soff = kr + rr * H_ + seg * 8;
            cp16(st + doff,          g_k + soff);
            cp16(st + COMP_B + doff, g_v + soff);
        }
    };

    float ot[8][4];
#pragma unroll
    for (int t = 0; t < 8; t++)
#pragma unroll
        for (int e = 0; e < 4; e++) ot[t][e] = 0.f;
    uint64_t L0 = 0, L1 = 0;

    const int R0 = qb * 128 + wrow0;

    wait_tile(jlo);
    fill_async(jlo, jlo & 1);
    cp_commit();

    for (int j0 = jlo; j0 < jhi; j0++) {
        cp_wait0();
        __syncthreads();
        if (j0 + 1 < jhi) {
            wait_tile(j0 + 1);
            fill_async(j0 + 1, (j0 + 1) & 1);
            cp_commit();
        }

        const int C0 = j0 * 64;
        if (C0 > R0 + 15) continue;

        const uint32_t st = sBase + (j0 & 1) * STAGE_B;
        const uint32_t sK = st, sV = st + COMP_B;

        // S = Q K^T (R8 ks-outer form)
        float sc[8][4];
#pragma unroll
        for (int t = 0; t < 8; t++)
#pragma unroll
            for (int e = 0; e < 4; e++) sc[t][e] = 0.f;

#pragma unroll
        for (int ks = 0; ks < 4; ks++) {
#pragma unroll
            for (int p = 0; p < 4; p++) {
                int brow = p * 16 + (lane & 7) + ((lane & 16) >> 1);
                int bcol = ks * 16 + (lane & 8);
                uint32_t boff = (uint32_t)(brow * AS + bcol) * 2;
                uint32_t bh[4];
                ldsm_x4(bh[0], bh[1], bh[2], bh[3], sK + boff);
                mma16816h(sc[2 * p],     aQ[ks][0], aQ[ks][1], aQ[ks][2], aQ[ks][3], bh[0], bh[1]);
                mma16816h(sc[2 * p + 1], aQ[ks][0], aQ[ks][1], aQ[ks][2], aQ[ks][3], bh[2], bh[3]);
            }
        }

        const bool diag = (C0 + 63 > R0);
        const int rowA = R0 + g, rowB = rowA + 8;
#pragma unroll
        for (int ks = 0; ks < 4; ks++) {
            uint64_t PA0 = exp_pair(pk2(sc[2 * ks][0],     sc[2 * ks][1]));
            uint64_t PB0 = exp_pair(pk2(sc[2 * ks][2],     sc[2 * ks][3]));
            uint64_t PA1 = exp_pair(pk2(sc[2 * ks + 1][0], sc[2 * ks + 1][1]));
            uint64_t PB1 = exp_pair(pk2(sc[2 * ks + 1][2], sc[2 * ks + 1][3]));
            if (diag) {
                float a0, a1;
                int col0 = C0 + (2 * ks) * 8 + c2;
                int col1 = col0 + 8;
                upk2(PA0, a0, a1);
                if (col0 > rowA) a0 = 0.f;
                if (col0 + 1 > rowA) a1 = 0.f;
                PA0 = pk2(a0, a1);
                upk2(PB0, a0, a1);
                if (col0 > rowB) a0 = 0.f;
                if (col0 + 1 > rowB) a1 = 0.f;
                PB0 = pk2(a0, a1);
                upk2(PA1, a0, a1);
                if (col1 > rowA) a0 = 0.f;
                if (col1 + 1 > rowA) a1 = 0.f;
                PA1 = pk2(a0, a1);
                upk2(PB1, a0, a1);
                if (col1 > rowB) a0 = 0.f;
                if (col1 + 1 > rowB) a1 = 0.f;
                PB1 = pk2(a0, a1);
            }
            L0 = f2add(L0, f2add(PA0, PA1));
            L1 = f2add(L1, f2add(PB0, PB1));

            uint32_t ph[4];
            ph[0] = pkh2p(PA0);
            ph[1] = pkh2p(PB0);
            ph[2] = pkh2p(PA1);
            ph[3] = pkh2p(PB1);
#pragma unroll
            for (int p = 0; p < 4; p++) {
                int vj = ks * 16 + (lane & 7) + (lane & 8);
                int vh = p * 16 + ((lane & 16) >> 1);
                uint32_t boff = (uint32_t)(vj * AS + vh) * 2;
                uint32_t bh[4];
                ldsm_x4_t(bh[0], bh[1], bh[2], bh[3], sV + boff);
                mma16816h(ot[2 * p],     ph[0], ph[1], ph[2], ph[3], bh[0], bh[1]);
                mma16816h(ot[2 * p + 1], ph[0], ph[1], ph[2], ph[3], bh[2], bh[3]);
            }
        }
    }

    // reduce row sums
    float la, lb, l0, l1;
    upk2(L0, la, lb); l0 = la + lb;
    upk2(L1, la, lb); l1 = la + lb;
    l0 += __shfl_xor_sync(0xffffffffu, l0, 1);
    l0 += __shfl_xor_sync(0xffffffffu, l0, 2);
    l1 += __shfl_xor_sync(0xffffffffu, l1, 1);
    l1 += __shfl_xor_sync(0xffffffffu, l1, 2);

    if (np == 1) {
        float inv0 = 1.0f / l0, inv1 = 1.0f / l1;
        const size_t rA = qrow + wrow0 + g;
        const size_t rB = rA + 8;
#pragma unroll
        for (int nt = 0; nt < 8; nt++) {
            *(float2*)&out[rA * H_ + nt * 8 + c2] =
                make_float2(ot[nt][0] * inv0, ot[nt][1] * inv0);
            *(float2*)&out[rB * H_ + nt * 8 + c2] =
                make_float2(ot[nt][2] * inv1, ot[nt][3] * inv1);
        }
        return;
    }

    // write partials (combine kernel normalizes after kernel boundary)
    float* po = g_po + ((size_t)(b * 40 + idx) * 8192);
    float* pl = g_pl + ((size_t)(b * 40 + idx) * 128);
    const int rowA = wrow0 + g;
#pragma unroll
    for (int nt = 0; nt < 8; nt++) {
        *(float2*)&po[rowA * 64 + nt * 8 + c2] = make_float2(ot[nt][0], ot[nt][1]);
        *(float2*)&po[(rowA + 8) * 64 + nt * 8 + c2] = make_float2(ot[nt][2], ot[nt][3]);
    }
    if ((lane & 3) == 0) {
        pl[rowA] = l0;
        pl[rowA + 8] = l1;
    }
}

__global__ __launch_bounds__(256, 2) void fused_kernel(float* __restrict__ out,
                                                       const float* __restrict__ x,
                                                       const float* __restrict__ Wk,
                                                       const float* __restrict__ Wq,
                                                       const float* __restrict__ Wv)
{
    extern __shared__ __align__(16) char smb[];
    if (blockIdx.x < 16)       wconv_body(Wk, Wq, Wv);
    else if (blockIdx.x < 272) proj_body(x, smb);
    else                       attn_body(out, smb);
}

// ---------------------------------------------------------------------------
// Combine pieces + normalize for qb >= 4. grid = B*12*8 (16-row slices).
// ---------------------------------------------------------------------------
__global__ __launch_bounds__(128) void combine_kernel(float* __restrict__ out)
{
    const int u  = blockIdx.x;
    const int b  = u / 96;
    const int rem = u % 96;
    const int qb = 4 + (rem >> 3);
    const int eighth = rem & 7;
    int start, np;
    if (qb < 8)       { start = 4 + 2 * (qb - 4);   np = 2; }
    else if (qb < 12) { start = 12 + 3 * (qb - 8);  np = 3; }
    else              { start = 24 + 4 * (qb - 12); np = 4; }

    const int tid = threadIdx.x;
    const int row = eighth * 16 + (tid >> 3);
    const int col0 = (tid & 7) * 8;

    const float* po = g_po + ((size_t)(b * 40 + start) * 8192);
    const float* pl = g_pl + ((size_t)(b * 40 + start) * 128);

    float l = 0.f;
#pragma unroll 4
    for (int p = 0; p < np; p++) l += pl[p * 128 + row];
    float inv = 1.0f / l;

    const size_t obase = ((size_t)(b * T_ + qb * 128 + row)) * H_;
#pragma unroll
    for (int k = 0; k < 2; k++) {
        int col = col0 + k * 4;
        float4 a = *(const float4*)&po[row * 64 + col];
#pragma unroll 4
        for (int p = 1; p < np; p++) {
            float4 c = *(const float4*)&po[p * 8192 + row * 64 + col];
            a.x += c.x; a.y += c.y; a.z += c.z; a.w += c.w;
        }
        *(float4*)&out[obase + col] =
            make_float4(a.x * inv, a.y * inv, a.z * inv, a.w * inv);
    }
}

// ---------------------------------------------------------------------------
extern "C" void kernel_launch(void* const* d_in, const int* in_sizes, int n_in,
                              void* d_out, int out_size)
{
    const float* x  = (const float*)d_in[0];
    const float* Wk = (const float*)d_in[1];
    const float* Wq = (const float*)d_in[2];
    const float* Wv = (const float*)d_in[3];
    float* out = (float*)d_out;

    cudaFuncSetAttribute(fused_kernel, cudaFuncAttributeMaxDynamicSharedMemorySize, FUSED_SMEM);
    fused_kernel<<<592, 256, FUSED_SMEM>>>(out, x, Wk, Wq, Wv);

    combine_kernel<<<B_ * 96, 128>>>(out);
}